// round 12
// baseline (speedup 1.0000x reference)
#include <cuda_runtime.h>
#include <cuda_fp16.h>
#include <cstdint>

#define BATCH 32
#define C 512
#define HW 3136
#define HID 128
#define TILES 25
#define PITCH 136                 // halves per row (272B), conflict-free ldsm
#define REGION (HID * PITCH)      // halves per 128-row region
#define EPS_BN 1e-5f
#define SMEM_BYTES (3 * REGION * 2)   // 104448 B -> 2 CTAs/SM (208,896 <= 227KB)

__device__ __align__(16) __half g_w1[2*HID*C];
__device__ __align__(16) __half g_w2[2*C*HID];
__device__ float g_ss[2*2*HID];

__global__ void prep_kernel(const float* __restrict__ w1r, const float* __restrict__ w1i,
                            const float* __restrict__ w2r, const float* __restrict__ w2i,
                            const float* __restrict__ rmr, const float* __restrict__ rvr,
                            const float* __restrict__ gr,  const float* __restrict__ bbr,
                            const float* __restrict__ rmi, const float* __restrict__ rvi,
                            const float* __restrict__ gi,  const float* __restrict__ bbi)
{
    int idx = blockIdx.x * blockDim.x + threadIdx.x;
    if (idx < HID * C) {
        g_w1[idx]         = __float2half_rn(w1r[idx]);
        g_w1[HID*C + idx] = __float2half_rn(w1i[idx]);
        g_w2[idx]         = __float2half_rn(w2r[idx]);
        g_w2[C*HID + idx] = __float2half_rn(w2i[idx]);
    }
    if (idx < HID) {
        float s0 = gr[idx] / sqrtf(rvr[idx] + EPS_BN);
        g_ss[idx]         = s0;
        g_ss[HID + idx]   = bbr[idx] - rmr[idx] * s0;
        float s1 = gi[idx] / sqrtf(rvi[idx] + EPS_BN);
        g_ss[2*HID + idx] = s1;
        g_ss[3*HID + idx] = bbi[idx] - rmi[idx] * s1;
    }
}

__device__ __forceinline__ void cp16(uint32_t dst_smem, const void* src) {
    asm volatile("cp.async.cg.shared.global [%0], [%1], 16;\n" :: "r"(dst_smem), "l"(src));
}
#define CP_COMMIT() asm volatile("cp.async.commit_group;\n" ::)
#define CP_WAIT0()  asm volatile("cp.async.wait_group 0;\n" ::)

__device__ __forceinline__ void ldsm4a(uint32_t r[4], uint32_t a) {
    asm volatile("ldmatrix.sync.aligned.m8n8.x4.shared.b16 {%0,%1,%2,%3}, [%4];"
                 : "=r"(r[0]), "=r"(r[1]), "=r"(r[2]), "=r"(r[3]) : "r"(a));
}
__device__ __forceinline__ void ldsm4ta(uint32_t r[4], uint32_t a) {
    asm volatile("ldmatrix.sync.aligned.m8n8.x4.trans.shared.b16 {%0,%1,%2,%3}, [%4];"
                 : "=r"(r[0]), "=r"(r[1]), "=r"(r[2]), "=r"(r[3]) : "r"(a));
}
__device__ __forceinline__ void mma_fp16(float d[4], const uint32_t a[4], uint32_t b0, uint32_t b1) {
    asm volatile("mma.sync.aligned.m16n8k16.row.col.f32.f16.f16.f32 "
                 "{%0,%1,%2,%3}, {%4,%5,%6,%7}, {%8,%9}, {%0,%1,%2,%3};"
                 : "+f"(d[0]), "+f"(d[1]), "+f"(d[2]), "+f"(d[3])
                 : "r"(a[0]), "r"(a[1]), "r"(a[2]), "r"(a[3]), "r"(b0), "r"(b1));
}

__global__ __launch_bounds__(512, 2)
void fused_kernel(const float* __restrict__ x, const int* __restrict__ mod,
                  float* __restrict__ out)
{
    extern __shared__ __align__(16) __half smem[];
    const uint32_t sb = (uint32_t)__cvta_generic_to_shared(smem);
    __half* sH = smem;
    __half* sW = smem + REGION;
    __half* sX = smem + 2 * REGION;
    const uint32_t SWb = sb + REGION * 2;
    const uint32_t SXb = sb + 4 * REGION;
    const uint32_t SHb = sb;

    const int tid  = threadIdx.x;
    const int warp = tid >> 5, lane = tid & 31;
    const int bimg = blockIdx.x / TILES;
    const int tile = blockIdx.x % TILES;
    const int p0   = tile * 128;
    const int br   = (__ldg(&mod[bimg]) == 1) ? 0 : 1;
    const int wr = warp >> 2, wc = warp & 3;       // 4x4 grid of 32x32 warp tiles
    const int g  = lane >> 2, tg = lane & 3;
    const int l16 = lane & 15, lh = lane >> 4;

    const float* xb = x   + (size_t)bimg * C * HW;
    float*       ob = out + (size_t)bimg * C * HW;
    const __half* w1 = g_w1 + br * HID * C;
    const __half* w2 = g_w2 + br * C * HID;

    // per-warp ldsm base offsets (bytes)
    const uint32_t aRow = (32*wr + l16) * PITCH + 8*lh;       // + ks
    const uint32_t bCol = l16 * PITCH + 32*wc + 8*lh;         // + ks*PITCH (+16 for nf=1)

    // ---- fill helpers (512 threads) ----
    auto fillW = [&](const __half* src, int ldsrc) {   // 128 x 128 halves -> sW
        #pragma unroll
        for (int t = 0; t < 4; t++) {
            int idx = tid + t * 512;
            int r = idx >> 4, c8 = (idx & 15) << 3;
            cp16(SWb + (r * PITCH + c8) * 2, src + (size_t)r * ldsrc + c8);
        }
    };
    auto fillX = [&](int kc) {                          // 128 ch x 128 px fp32 -> fp16
        #pragma unroll
        for (int b = 0; b < 2; b++) {
            float4 v[4];
            #pragma unroll
            for (int t = 0; t < 4; t++) {
                int idx = tid + (b * 4 + t) * 512;
                int row = idx >> 5;
                int pg  = (idx & 31) << 2;
                int gp  = p0 + pg; if (gp > HW - 4) gp = HW - 4;  // clamp; tail never stored
                v[t] = *(const float4*)(xb + (size_t)(kc + row) * HW + gp);
            }
            #pragma unroll
            for (int t = 0; t < 4; t++) {
                int idx = tid + (b * 4 + t) * 512;
                int row = idx >> 5;
                int pg  = (idx & 31) << 2;
                *(__half2*)&sX[row * PITCH + pg]     = __floats2half2_rn(v[t].x, v[t].y);
                *(__half2*)&sX[row * PITCH + pg + 2] = __floats2half2_rn(v[t].z, v[t].w);
            }
        }
    };

    float acc[2][4][4];
    #pragma unroll
    for (int a = 0; a < 2; a++)
        #pragma unroll
        for (int b2 = 0; b2 < 4; b2++)
            #pragma unroll
            for (int c2 = 0; c2 < 4; c2++) acc[a][b2][c2] = 0.f;

    // ============ Phase A: D1[128 hid x 128 px] = W1 . X, K=512 in 4 chunks of 128 ============
    for (int i = 0; i < 4; i++) {
        __syncthreads();                       // prior gemm done with sW/sX
        fillW(w1 + i * 128, C); CP_COMMIT();
        fillX(i * 128);
        CP_WAIT0(); __syncthreads();
        #pragma unroll
        for (int ks = 0; ks < 128; ks += 16) {
            uint32_t Af[2][4];
            #pragma unroll
            for (int mf = 0; mf < 2; mf++)
                ldsm4a(Af[mf], SWb + (aRow + 16*mf*PITCH + ks) * 2);
            uint32_t Bf[2][4];
            #pragma unroll
            for (int nf = 0; nf < 2; nf++)
                ldsm4ta(Bf[nf], SXb + (bCol + ks*PITCH + 16*nf) * 2);
            #pragma unroll
            for (int mf = 0; mf < 2; mf++)
                #pragma unroll
                for (int nf = 0; nf < 2; nf++) {
                    mma_fp16(acc[mf][nf*2 + 0], Af[mf], Bf[nf][0], Bf[nf][1]);
                    mma_fp16(acc[mf][nf*2 + 1], Af[mf], Bf[nf][2], Bf[nf][3]);
                }
        }
    }

    // ---- transition: prefetch W2(0); epilogue A (BN+ReLU -> fp16 h in sH) ----
    __syncthreads();                           // all gemm A done; sW free
    fillW(w2, HID); CP_COMMIT();
    #pragma unroll
    for (int mf = 0; mf < 2; mf++)
        #pragma unroll
        for (int rh = 0; rh < 2; rh++) {
            int row = 32*wr + 16*mf + 8*rh + g;
            float sc = g_ss[br*2*HID + row];
            float sh = g_ss[br*2*HID + HID + row];
            #pragma unroll
            for (int n8 = 0; n8 < 4; n8++) {
                int col = 32*wc + 8*n8 + 2*tg;
                float v0 = fmaxf(fmaf(acc[mf][n8][2*rh+0], sc, sh), 0.f);
                float v1 = fmaxf(fmaf(acc[mf][n8][2*rh+1], sc, sh), 0.f);
                *(__half2*)&sH[row * PITCH + col] = __floats2half2_rn(v0, v1);
            }
        }
    CP_WAIT0(); __syncthreads();               // sH + W2 chunk 0 visible

    // ============ Phase B: out = W2 . h, K=128, 4 chunks of 128 channels ============
    for (int j = 0; j < 4; j++) {
        #pragma unroll
        for (int a = 0; a < 2; a++)
            #pragma unroll
            for (int b2 = 0; b2 < 4; b2++)
                #pragma unroll
                for (int c2 = 0; c2 < 4; c2++) acc[a][b2][c2] = 0.f;

        #pragma unroll
        for (int ks = 0; ks < 128; ks += 16) {
            uint32_t Af[2][4];
            #pragma unroll
            for (int mf = 0; mf < 2; mf++)
                ldsm4a(Af[mf], SWb + (aRow + 16*mf*PITCH + ks) * 2);
            uint32_t Bf[2][4];
            #pragma unroll
            for (int nf = 0; nf < 2; nf++)
                ldsm4ta(Bf[nf], SHb + (bCol + ks*PITCH + 16*nf) * 2);
            #pragma unroll
            for (int mf = 0; mf < 2; mf++)
                #pragma unroll
                for (int nf = 0; nf < 2; nf++) {
                    mma_fp16(acc[mf][nf*2 + 0], Af[mf], Bf[nf][0], Bf[nf][1]);
                    mma_fp16(acc[mf][nf*2 + 1], Af[mf], Bf[nf][2], Bf[nf][3]);
                }
        }
        __syncthreads();                       // all warps done reading sW chunk j
        if (j < 3) { fillW(w2 + (size_t)(j + 1) * 128 * HID, HID); CP_COMMIT(); }

        // store chunk j (overlaps in-flight cp.async)
        const int cc = j * 128;
        #pragma unroll
        for (int mf = 0; mf < 2; mf++)
            #pragma unroll
            for (int rh = 0; rh < 2; rh++) {
                int row = cc + 32*wr + 16*mf + 8*rh + g;
                #pragma unroll
                for (int n8 = 0; n8 < 4; n8++) {
                    int col = 32*wc + 8*n8 + 2*tg;
                    if (p0 + col < HW) {
                        float2 v = make_float2(acc[mf][n8][2*rh], acc[mf][n8][2*rh+1]);
                        *(float2*)&ob[(size_t)row * HW + p0 + col] = v;
                    }
                }
            }
        if (j < 3) { CP_WAIT0(); __syncthreads(); }
    }
}

extern "C" void kernel_launch(void* const* d_in, const int* in_sizes, int n_in,
                              void* d_out, int out_size)
{
    (void)in_sizes; (void)n_in; (void)out_size;
    const float* x   = (const float*)d_in[0];
    const int*   md  = (const int*)  d_in[1];
    const float* w1r = (const float*)d_in[2];
    const float* rmr = (const float*)d_in[3];
    const float* rvr = (const float*)d_in[4];
    const float* gr  = (const float*)d_in[5];
    const float* bbr = (const float*)d_in[6];
    const float* w2r = (const float*)d_in[7];
    const float* w1i = (const float*)d_in[8];
    const float* rmi = (const float*)d_in[9];
    const float* rvi = (const float*)d_in[10];
    const float* gi  = (const float*)d_in[11];
    const float* bbi = (const float*)d_in[12];
    const float* w2i = (const float*)d_in[13];
    float* out = (float*)d_out;

    cudaFuncSetAttribute(fused_kernel, cudaFuncAttributeMaxDynamicSharedMemorySize, SMEM_BYTES);

    prep_kernel<<<(HID * C + 255) / 256, 256>>>(w1r, w1i, w2r, w2i,
                                                rmr, rvr, gr, bbr,
                                                rmi, rvi, gi, bbi);
    fused_kernel<<<BATCH * TILES, 512, SMEM_BYTES>>>(x, md, out);
}